// round 9
// baseline (speedup 1.0000x reference)
#include <cuda_runtime.h>
#include <cstdint>
#include <cstddef>

// Problem constants
#define B_ROWS 8192
#define FEAT   7680
#define HID    512

// Scratch activations (allocation-free: __device__ globals)
__device__ float g_h1[(size_t)B_ROWS * HID];
__device__ float g_h2[(size_t)B_ROWS * HID];
__device__ int   g_idx64;

// ---------------------------------------------------------------------------
// helpers
// ---------------------------------------------------------------------------
__device__ __forceinline__ uint32_t f2tf32(float x) {
    uint32_t r;
    asm("cvt.rna.tf32.f32 %0, %1;" : "=r"(r) : "f"(x));
    return r;
}

__device__ __forceinline__ void cp_async16(uint32_t smem_dst, const void* gptr) {
    asm volatile("cp.async.cg.shared.global [%0], [%1], 16;"
                 :: "r"(smem_dst), "l"(gptr));
}

__device__ __forceinline__ void cp_commit() {
    asm volatile("cp.async.commit_group;");
}

// ---------------------------------------------------------------------------
// scene_idx dtype detection (int32 vs int64).
// int64 values in [0,72) -> every odd 32-bit word is 0.
// ---------------------------------------------------------------------------
__global__ void detect_idx_kernel(const int* __restrict__ p) {
    int is64 = 1;
    for (int i = 0; i < 64; i++) {
        if (p[2 * i + 1] != 0) { is64 = 0; break; }
    }
    g_idx64 = is64;
}

// ---------------------------------------------------------------------------
// Pipelined TF32 GEMM:  C[M,N] = act( A[M,K] @ B[N,K]^T + bias[N] )
// A row-major [M,K], B row-major [N,K]  (torch Linear weight layout)
// CTA tile 128x256x32, 8 warps arranged 2(M) x 4(N), warp tile 64x64 via
// m16n8k8 tf32 (mi=4, ni=8 -> 32 MMAs per k8-step against 32 LDS + 32 CVT).
// Crossbar read traffic per kt: (4*BM + 2*BN)*BK*4 = 128KB -> 1024 cyc,
// balanced against ~1024 tensor cycles (was 1.5:1 crossbar-bound at 64x32).
// 3-stage cp.async pipeline, single __syncthreads per kt (loads for slot
// (kt-1)%3 are issued after the top barrier, which already orders them
// against all reads of that slot from iteration kt-1).
// ---------------------------------------------------------------------------
template<int BM, int BN, int BK, int STAGES, bool RELU>
__global__ void __launch_bounds__(256, 1) gemm_relu_tf32(
    const float* __restrict__ A, const float* __restrict__ Bw,
    const float* __restrict__ bias, float* __restrict__ C,
    int M, int N, int K)
{
    constexpr int SKA = BK + 4;                 // 36 floats per A row
    constexpr int SKB = BK + 4;                 // 36 floats per B row
    constexpr int STAGE_F = BM * SKA + BN * SKB;

    extern __shared__ float smem[];

    const int tid  = threadIdx.x;
    const int warp = tid >> 5;
    const int lane = tid & 31;
    const int g    = lane >> 2;   // group id (0..7)
    const int t4   = lane & 3;    // thread in group (0..3)

    const int m0 = blockIdx.y * BM;
    const int n0 = blockIdx.x * BN;

    const int wm = (warp & 1) * 64;   // warp M offset within CTA tile
    const int wn = (warp >> 1) * 64;  // warp N offset within CTA tile

    float acc[4][8][4];
    #pragma unroll
    for (int i = 0; i < 4; i++)
        #pragma unroll
        for (int j = 0; j < 8; j++)
            #pragma unroll
            for (int k = 0; k < 4; k++) acc[i][j][k] = 0.f;

    auto load_stage = [&](int s, int k0) {
        float* As = smem + s * STAGE_F;
        float* Bs = As + BM * SKA;
        constexpr int CPR = BK / 4;  // 16B chunks per row = 8
        #pragma unroll
        for (int i = 0; i < (BM * CPR) / 256; i++) {
            int q   = tid + i * 256;
            int row = q / CPR, c = q % CPR;
            cp_async16((uint32_t)__cvta_generic_to_shared(As + row * SKA + c * 4),
                       A + (size_t)(m0 + row) * K + k0 + c * 4);
        }
        #pragma unroll
        for (int i = 0; i < (BN * CPR) / 256; i++) {
            int q   = tid + i * 256;
            int row = q / CPR, c = q % CPR;
            cp_async16((uint32_t)__cvta_generic_to_shared(Bs + row * SKB + c * 4),
                       Bw + (size_t)(n0 + row) * K + k0 + c * 4);
        }
    };

    const int KT = K / BK;

    #pragma unroll
    for (int s = 0; s < STAGES - 1; s++) {
        load_stage(s, s * BK);
        cp_commit();
    }

    int buf = 0;
    for (int kt = 0; kt < KT; kt++) {
        asm volatile("cp.async.wait_group %0;" :: "n"(STAGES - 2));
        __syncthreads();

        // Issue next stage's loads immediately (targets slot (kt-1)%STAGES,
        // fully consumed in iteration kt-1; the barrier above orders it).
        int kn = kt + STAGES - 1;
        if (kn < KT) load_stage(kn % STAGES, kn * BK);
        cp_commit();

        const float* As = smem + buf * STAGE_F;
        const float* Bs = As + BM * SKA;

        #pragma unroll
        for (int kk = 0; kk < BK / 8; kk++) {
            uint32_t b[8][2];
            #pragma unroll
            for (int ni = 0; ni < 8; ni++) {
                const float* bp = Bs + (wn + ni * 8 + g) * SKB + kk * 8;
                b[ni][0] = f2tf32(bp[t4]);
                b[ni][1] = f2tf32(bp[t4 + 4]);
            }
            #pragma unroll
            for (int mi = 0; mi < 4; mi++) {
                uint32_t a[4];
                const float* ap  = As + (wm + mi * 16 + g) * SKA + kk * 8;
                const float* ap8 = ap + 8 * SKA;
                a[0] = f2tf32(ap[t4]);
                a[1] = f2tf32(ap8[t4]);
                a[2] = f2tf32(ap[t4 + 4]);
                a[3] = f2tf32(ap8[t4 + 4]);
                #pragma unroll
                for (int ni = 0; ni < 8; ni++) {
                    float* d = acc[mi][ni];
                    asm volatile(
                        "mma.sync.aligned.m16n8k8.row.col.f32.tf32.tf32.f32 "
                        "{%0,%1,%2,%3}, {%4,%5,%6,%7}, {%8,%9}, {%0,%1,%2,%3};"
                        : "+f"(d[0]), "+f"(d[1]), "+f"(d[2]), "+f"(d[3])
                        : "r"(a[0]), "r"(a[1]), "r"(a[2]), "r"(a[3]),
                          "r"(b[ni][0]), "r"(b[ni][1]));
                }
            }
        }

        buf++;
        if (buf == STAGES) buf = 0;
    }

    // Epilogue: bias + optional ReLU, float2 stores (cols 2t, 2t+1 contiguous)
    #pragma unroll
    for (int mi = 0; mi < 4; mi++) {
        int row0 = m0 + wm + mi * 16 + g;
        #pragma unroll
        for (int ni = 0; ni < 8; ni++) {
            int col = n0 + wn + ni * 8 + t4 * 2;
            float bb0 = bias[col], bb1 = bias[col + 1];
            float v0 = acc[mi][ni][0] + bb0;
            float v1 = acc[mi][ni][1] + bb1;
            float v2 = acc[mi][ni][2] + bb0;
            float v3 = acc[mi][ni][3] + bb1;
            if (RELU) {
                v0 = fmaxf(v0, 0.f); v1 = fmaxf(v1, 0.f);
                v2 = fmaxf(v2, 0.f); v3 = fmaxf(v3, 0.f);
            }
            *(float2*)(C + (size_t)row0 * N + col)       = make_float2(v0, v1);
            *(float2*)(C + (size_t)(row0 + 8) * N + col) = make_float2(v2, v3);
        }
    }
}

// ---------------------------------------------------------------------------
// Head: shared = h2 @ W3^T + b3 (N=4), then per-scene routed 2x2 transforms.
// One warp per output row.
// ---------------------------------------------------------------------------
__global__ void head_kernel(const float* __restrict__ h2,
                            const float* __restrict__ W3,
                            const float* __restrict__ b3,
                            const void* __restrict__ sidx,
                            const float* __restrict__ xyW,
                            const float* __restrict__ xyb,
                            const float* __restrict__ tW,
                            float* __restrict__ out)
{
    const int warp = threadIdx.x >> 5;
    const int lane = threadIdx.x & 31;
    const int row  = blockIdx.x * (blockDim.x >> 5) + warp;

    const float4* hp = (const float4*)(h2 + (size_t)row * HID);
    float acc[4] = {0.f, 0.f, 0.f, 0.f};
    #pragma unroll
    for (int j = 0; j < HID / 128; j++) {
        float4 hv = hp[lane + 32 * j];
        #pragma unroll
        for (int r = 0; r < 4; r++) {
            float4 wv = ((const float4*)(W3 + r * HID))[lane + 32 * j];
            acc[r] += hv.x * wv.x + hv.y * wv.y + hv.z * wv.z + hv.w * wv.w;
        }
    }
    #pragma unroll
    for (int r = 0; r < 4; r++)
        #pragma unroll
        for (int off = 16; off > 0; off >>= 1)
            acc[r] += __shfl_xor_sync(0xffffffffu, acc[r], off);

    if (lane == 0) {
        float s0 = acc[0] + b3[0];
        float s1 = acc[1] + b3[1];
        float s2 = acc[2] + b3[2];
        float s3 = acc[3] + b3[3];

        int s;
        if (g_idx64) s = (int)((const long long*)sidx)[row];
        else         s = ((const int*)sidx)[row];

        const float* wxy = xyW + s * 4;
        const float* wt  = tW  + s * 4;
        float o0 = wxy[0] * s0 + wxy[1] * s1 + xyb[s * 2 + 0];
        float o1 = wxy[2] * s0 + wxy[3] * s1 + xyb[s * 2 + 1];
        float o2 = wt[0] * s2 + wt[1] * s3;
        float o3 = wt[2] * s2 + wt[3] * s3;
        *(float4*)(out + (size_t)row * 4) = make_float4(o0, o1, o2, o3);
    }
}

// ---------------------------------------------------------------------------
// launch
// ---------------------------------------------------------------------------
extern "C" void kernel_launch(void* const* d_in, const int* in_sizes, int n_in,
                              void* d_out, int out_size)
{
    const float* feat = (const float*)d_in[0];
    const void*  sidx = d_in[1];
    const float* W1   = (const float*)d_in[2];
    const float* b1   = (const float*)d_in[3];
    const float* W2   = (const float*)d_in[4];
    const float* b2   = (const float*)d_in[5];
    const float* W3   = (const float*)d_in[6];
    const float* b3   = (const float*)d_in[7];
    const float* xyW  = (const float*)d_in[8];
    const float* xyb  = (const float*)d_in[9];
    const float* tW   = (const float*)d_in[10];
    float* out = (float*)d_out;

    float *h1, *h2;
    cudaGetSymbolAddress((void**)&h1, g_h1);
    cudaGetSymbolAddress((void**)&h2, g_h2);

    constexpr int BM = 128, BN = 256, BK = 32, STG = 3;
    constexpr int SMEM_BYTES = STG * (BM * (BK + 4) + BN * (BK + 4)) * (int)sizeof(float);

    cudaFuncSetAttribute(gemm_relu_tf32<BM, BN, BK, STG, true>,
                         cudaFuncAttributeMaxDynamicSharedMemorySize, SMEM_BYTES);

    detect_idx_kernel<<<1, 1>>>((const int*)sidx);

    dim3 grid1(HID / BN, B_ROWS / BM);   // (2, 64) = 128 CTAs
    // GEMM1: relu(feat @ W1^T + b1) -> h1
    gemm_relu_tf32<BM, BN, BK, STG, true><<<grid1, 256, SMEM_BYTES>>>(
        feat, W1, b1, h1, B_ROWS, HID, FEAT);
    // GEMM2: relu(h1 @ W2^T + b2) -> h2
    gemm_relu_tf32<BM, BN, BK, STG, true><<<grid1, 256, SMEM_BYTES>>>(
        h1, W2, b2, h2, B_ROWS, HID, HID);
    // Head
    head_kernel<<<B_ROWS / 8, 256>>>(h2, W3, b3, sidx, xyW, xyb, tW, out);
}

// round 10
// speedup vs baseline: 1.6253x; 1.6253x over previous
#include <cuda_runtime.h>
#include <cuda_fp16.h>
#include <cstdint>
#include <cstddef>

// Problem constants
#define B_ROWS 8192
#define FEAT   7680
#define HID    512

// Scratch (allocation-free: __device__ globals)
__device__ __half g_feat16[(size_t)B_ROWS * FEAT];   // 126 MB
__device__ __half g_w1h[(size_t)HID * FEAT];         // 7.9 MB
__device__ __half g_w2h[(size_t)HID * HID];          // 0.5 MB
__device__ __half g_h1[(size_t)B_ROWS * HID];        // 8.4 MB (fp16 activations)
__device__ float  g_h2[(size_t)B_ROWS * HID];        // 16.8 MB
__device__ int    g_idx64;

// ---------------------------------------------------------------------------
// helpers
// ---------------------------------------------------------------------------
__device__ __forceinline__ void cp_async16(uint32_t smem_dst, const void* gptr) {
    asm volatile("cp.async.cg.shared.global [%0], [%1], 16;"
                 :: "r"(smem_dst), "l"(gptr));
}
__device__ __forceinline__ void cp_commit() {
    asm volatile("cp.async.commit_group;");
}

// ---------------------------------------------------------------------------
// fp32 -> fp16 conversion (grid-stride, float4 -> 2x half2 packed as uint2)
// ---------------------------------------------------------------------------
__global__ void f32_to_f16_kernel(const float4* __restrict__ in,
                                  uint2* __restrict__ out, int n4)
{
    int stride = gridDim.x * blockDim.x;
    for (int i = blockIdx.x * blockDim.x + threadIdx.x; i < n4; i += stride) {
        float4 v = in[i];
        __half2 h01 = __floats2half2_rn(v.x, v.y);
        __half2 h23 = __floats2half2_rn(v.z, v.w);
        uint2 u;
        u.x = *(uint32_t*)&h01;
        u.y = *(uint32_t*)&h23;
        out[i] = u;
    }
}

// ---------------------------------------------------------------------------
// scene_idx dtype detection (int32 vs int64).
// ---------------------------------------------------------------------------
__global__ void detect_idx_kernel(const int* __restrict__ p) {
    int is64 = 1;
    for (int i = 0; i < 64; i++) {
        if (p[2 * i + 1] != 0) { is64 = 0; break; }
    }
    g_idx64 = is64;
}

// ---------------------------------------------------------------------------
// Pipelined FP16 GEMM (f32 accumulate):
//   C[M,N] = act( A[M,K] @ B[N,K]^T + bias[N] ),  A/B fp16, C fp32 or fp16
// CTA tile 128x256x64, 8 warps 2(M) x 4(N), warp tile 64x64 via m16n8k16.
// Per kt per warp: 128 LDS.32 (fragments are contiguous f16 pairs, no CVT)
// + 128 HMMA(k16). Crossbar ~512 cyc/kt vs tensor ~4096 -> tensor-bound.
// 4-stage cp.async pipeline, single __syncthreads per kt.
// SMEM rows padded 64 -> 72 halves (144B): fragment LDS bank = (4g+t4)%32,
// conflict-free; cp.async 16B chunks stay 16B-aligned (144 = 9*16).
// ---------------------------------------------------------------------------
template<int BM, int BN, int BK, int STAGES, bool RELU, typename OutT>
__global__ void __launch_bounds__(256, 1) gemm_relu_f16(
    const __half* __restrict__ A, const __half* __restrict__ Bw,
    const float* __restrict__ bias, OutT* __restrict__ C,
    int M, int N, int K)
{
    constexpr int SKA = BK + 8;                 // halves per A row (72)
    constexpr int SKB = BK + 8;                 // halves per B row
    constexpr int STAGE_H = BM * SKA + BN * SKB;

    extern __shared__ __half smem[];

    const int tid  = threadIdx.x;
    const int warp = tid >> 5;
    const int lane = tid & 31;
    const int g    = lane >> 2;   // group id (0..7)
    const int t4   = lane & 3;    // thread in group (0..3)

    const int m0 = blockIdx.y * BM;
    const int n0 = blockIdx.x * BN;

    const int wm = (warp & 1) * 64;   // warp M offset
    const int wn = (warp >> 1) * 64;  // warp N offset

    float acc[4][8][4];
    #pragma unroll
    for (int i = 0; i < 4; i++)
        #pragma unroll
        for (int j = 0; j < 8; j++)
            #pragma unroll
            for (int k = 0; k < 4; k++) acc[i][j][k] = 0.f;

    auto load_stage = [&](int s, int k0) {
        __half* As = smem + s * STAGE_H;
        __half* Bs = As + BM * SKA;
        constexpr int CPR = (BK * 2) / 16;  // 16B chunks per row = 8
        #pragma unroll
        for (int i = 0; i < (BM * CPR) / 256; i++) {
            int q   = tid + i * 256;
            int row = q / CPR, c = q % CPR;
            cp_async16((uint32_t)__cvta_generic_to_shared(As + row * SKA + c * 8),
                       A + (size_t)(m0 + row) * K + k0 + c * 8);
        }
        #pragma unroll
        for (int i = 0; i < (BN * CPR) / 256; i++) {
            int q   = tid + i * 256;
            int row = q / CPR, c = q % CPR;
            cp_async16((uint32_t)__cvta_generic_to_shared(Bs + row * SKB + c * 8),
                       Bw + (size_t)(n0 + row) * K + k0 + c * 8);
        }
    };

    const int KT = K / BK;

    #pragma unroll
    for (int s = 0; s < STAGES - 1; s++) {
        load_stage(s, s * BK);
        cp_commit();
    }

    int buf = 0;
    for (int kt = 0; kt < KT; kt++) {
        asm volatile("cp.async.wait_group %0;" :: "n"(STAGES - 2));
        __syncthreads();

        // Next stage targets slot (kt-1)%STAGES, fully consumed last iter;
        // the barrier above orders it.
        int kn = kt + STAGES - 1;
        if (kn < KT) load_stage(kn % STAGES, kn * BK);
        cp_commit();

        const __half* As = smem + buf * STAGE_H;
        const __half* Bs = As + BM * SKA;

        #pragma unroll
        for (int kk = 0; kk < BK / 16; kk++) {
            uint32_t b[8][2];
            #pragma unroll
            for (int ni = 0; ni < 8; ni++) {
                const __half* bp = Bs + (wn + ni * 8 + g) * SKB + kk * 16 + t4 * 2;
                b[ni][0] = *(const uint32_t*)bp;        // Bw[n][2t4, 2t4+1]
                b[ni][1] = *(const uint32_t*)(bp + 8);  // Bw[n][2t4+8, 2t4+9]
            }
            #pragma unroll
            for (int mi = 0; mi < 4; mi++) {
                const __half* ap  = As + (wm + mi * 16 + g) * SKA + kk * 16 + t4 * 2;
                const __half* ap8 = ap + 8 * SKA;
                uint32_t a0 = *(const uint32_t*)ap;
                uint32_t a1 = *(const uint32_t*)ap8;
                uint32_t a2 = *(const uint32_t*)(ap + 8);
                uint32_t a3 = *(const uint32_t*)(ap8 + 8);
                #pragma unroll
                for (int ni = 0; ni < 8; ni++) {
                    float* d = acc[mi][ni];
                    asm volatile(
                        "mma.sync.aligned.m16n8k16.row.col.f32.f16.f16.f32 "
                        "{%0,%1,%2,%3}, {%4,%5,%6,%7}, {%8,%9}, {%0,%1,%2,%3};"
                        : "+f"(d[0]), "+f"(d[1]), "+f"(d[2]), "+f"(d[3])
                        : "r"(a0), "r"(a1), "r"(a2), "r"(a3),
                          "r"(b[ni][0]), "r"(b[ni][1]));
                }
            }
        }

        buf++;
        if (buf == STAGES) buf = 0;
    }

    // Epilogue: bias + optional ReLU; cols (2t4, 2t4+1) contiguous.
    #pragma unroll
    for (int mi = 0; mi < 4; mi++) {
        int row0 = m0 + wm + mi * 16 + g;
        #pragma unroll
        for (int ni = 0; ni < 8; ni++) {
            int col = n0 + wn + ni * 8 + t4 * 2;
            float bb0 = bias[col], bb1 = bias[col + 1];
            float v0 = acc[mi][ni][0] + bb0;
            float v1 = acc[mi][ni][1] + bb1;
            float v2 = acc[mi][ni][2] + bb0;
            float v3 = acc[mi][ni][3] + bb1;
            if (RELU) {
                v0 = fmaxf(v0, 0.f); v1 = fmaxf(v1, 0.f);
                v2 = fmaxf(v2, 0.f); v3 = fmaxf(v3, 0.f);
            }
            if (sizeof(OutT) == 2) {
                __half2* p0 = (__half2*)((__half*)C + (size_t)row0 * N + col);
                __half2* p1 = (__half2*)((__half*)C + (size_t)(row0 + 8) * N + col);
                *p0 = __floats2half2_rn(v0, v1);
                *p1 = __floats2half2_rn(v2, v3);
            } else {
                *(float2*)((float*)C + (size_t)row0 * N + col)       = make_float2(v0, v1);
                *(float2*)((float*)C + (size_t)(row0 + 8) * N + col) = make_float2(v2, v3);
            }
        }
    }
}

// ---------------------------------------------------------------------------
// Head: shared = h2 @ W3^T + b3 (N=4), then per-scene routed 2x2 transforms.
// ---------------------------------------------------------------------------
__global__ void head_kernel(const float* __restrict__ h2,
                            const float* __restrict__ W3,
                            const float* __restrict__ b3,
                            const void* __restrict__ sidx,
                            const float* __restrict__ xyW,
                            const float* __restrict__ xyb,
                            const float* __restrict__ tW,
                            float* __restrict__ out)
{
    const int warp = threadIdx.x >> 5;
    const int lane = threadIdx.x & 31;
    const int row  = blockIdx.x * (blockDim.x >> 5) + warp;

    const float4* hp = (const float4*)(h2 + (size_t)row * HID);
    float acc[4] = {0.f, 0.f, 0.f, 0.f};
    #pragma unroll
    for (int j = 0; j < HID / 128; j++) {
        float4 hv = hp[lane + 32 * j];
        #pragma unroll
        for (int r = 0; r < 4; r++) {
            float4 wv = ((const float4*)(W3 + r * HID))[lane + 32 * j];
            acc[r] += hv.x * wv.x + hv.y * wv.y + hv.z * wv.z + hv.w * wv.w;
        }
    }
    #pragma unroll
    for (int r = 0; r < 4; r++)
        #pragma unroll
        for (int off = 16; off > 0; off >>= 1)
            acc[r] += __shfl_xor_sync(0xffffffffu, acc[r], off);

    if (lane == 0) {
        float s0 = acc[0] + b3[0];
        float s1 = acc[1] + b3[1];
        float s2 = acc[2] + b3[2];
        float s3 = acc[3] + b3[3];

        int s;
        if (g_idx64) s = (int)((const long long*)sidx)[row];
        else         s = ((const int*)sidx)[row];

        const float* wxy = xyW + s * 4;
        const float* wt  = tW  + s * 4;
        float o0 = wxy[0] * s0 + wxy[1] * s1 + xyb[s * 2 + 0];
        float o1 = wxy[2] * s0 + wxy[3] * s1 + xyb[s * 2 + 1];
        float o2 = wt[0] * s2 + wt[1] * s3;
        float o3 = wt[2] * s2 + wt[3] * s3;
        *(float4*)(out + (size_t)row * 4) = make_float4(o0, o1, o2, o3);
    }
}

// ---------------------------------------------------------------------------
// launch
// ---------------------------------------------------------------------------
extern "C" void kernel_launch(void* const* d_in, const int* in_sizes, int n_in,
                              void* d_out, int out_size)
{
    const float* feat = (const float*)d_in[0];
    const void*  sidx = d_in[1];
    const float* W1   = (const float*)d_in[2];
    const float* b1   = (const float*)d_in[3];
    const float* W2   = (const float*)d_in[4];
    const float* b2   = (const float*)d_in[5];
    const float* W3   = (const float*)d_in[6];
    const float* b3   = (const float*)d_in[7];
    const float* xyW  = (const float*)d_in[8];
    const float* xyb  = (const float*)d_in[9];
    const float* tW   = (const float*)d_in[10];
    float* out = (float*)d_out;

    __half *feat16, *w1h, *w2h, *h1;
    float *h2;
    cudaGetSymbolAddress((void**)&feat16, g_feat16);
    cudaGetSymbolAddress((void**)&w1h, g_w1h);
    cudaGetSymbolAddress((void**)&w2h, g_w2h);
    cudaGetSymbolAddress((void**)&h1, g_h1);
    cudaGetSymbolAddress((void**)&h2, g_h2);

    constexpr int BM = 128, BN = 256, BK = 64, STG = 4;
    constexpr int SMEM_BYTES = STG * (BM * (BK + 8) + BN * (BK + 8)) * 2;

    cudaFuncSetAttribute(gemm_relu_f16<BM, BN, BK, STG, true, __half>,
                         cudaFuncAttributeMaxDynamicSharedMemorySize, SMEM_BYTES);
    cudaFuncSetAttribute(gemm_relu_f16<BM, BN, BK, STG, true, float>,
                         cudaFuncAttributeMaxDynamicSharedMemorySize, SMEM_BYTES);

    detect_idx_kernel<<<1, 1>>>((const int*)sidx);

    // Pre-convert inputs to fp16 (bandwidth-bound, ~55us total)
    f32_to_f16_kernel<<<1184, 256>>>((const float4*)feat, (uint2*)feat16,
                                     (B_ROWS * FEAT) / 4);
    f32_to_f16_kernel<<<256, 256>>>((const float4*)W1, (uint2*)w1h,
                                    (HID * FEAT) / 4);
    f32_to_f16_kernel<<<64, 256>>>((const float4*)W2, (uint2*)w2h,
                                   (HID * HID) / 4);

    dim3 grid(HID / BN, B_ROWS / BM);   // (2, 64) = 128 CTAs
    // GEMM1: relu(feat @ W1^T + b1) -> h1 (fp16)
    gemm_relu_f16<BM, BN, BK, STG, true, __half><<<grid, 256, SMEM_BYTES>>>(
        feat16, w1h, b1, h1, B_ROWS, HID, FEAT);
    // GEMM2: relu(h1 @ W2^T + b2) -> h2 (fp32)
    gemm_relu_f16<BM, BN, BK, STG, true, float><<<grid, 256, SMEM_BYTES>>>(
        h1, w2h, b2, h2, B_ROWS, HID, HID);
    // Head
    head_kernel<<<B_ROWS / 8, 256>>>(h2, W3, b3, sidx, xyW, xyb, tW, out);
}